// round 6
// baseline (speedup 1.0000x reference)
#include <cuda_runtime.h>
#include <math.h>
#include <stdint.h>

#define NN 30000
#define NE 480000
#define FDIM 192
#define DX 64
#define LV 256
#define LT 100

// ---------------- scratch arenas (no allocs allowed) ----------------
__device__ float g_farena[44000000];
__device__ int   g_iarena[1600000];

// ---------------- graph build ----------------
__global__ void k_detect(const void* ei, int* is64) {
    const int* p = (const int*)ei;
    int zeros = 0;
    for (int i = 1; i < 256; i += 2) if (p[i] == 0) zeros++;
    *is64 = (zeros >= 120) ? 1 : 0;
}

__global__ void k_zero_i(int* a, int n) {
    int i = blockIdx.x * blockDim.x + threadIdx.x;
    if (i < n) a[i] = 0;
}

__global__ void k_convert_hist(const void* ei, int* src, int* dst,
                               int* cnt, int* degs, const int* is64) {
    int e = blockIdx.x * blockDim.x + threadIdx.x;
    if (e >= NE) return;
    int s, d;
    if (*is64) {
        const long long* p = (const long long*)ei;
        s = (int)p[e];
        d = (int)p[NE + e];
    } else {
        const int* p = (const int*)ei;
        s = p[e];
        d = p[NE + e];
    }
    src[e] = s;
    dst[e] = d;
    atomicAdd(&cnt[d], 1);
    atomicAdd(&degs[s], 1);
}

// 1024 threads, 30 counts/thread + warp-shuffle hierarchical scan
__global__ void __launch_bounds__(1024)
k_scan(const int* __restrict__ cnt, int* __restrict__ off, int* __restrict__ cur,
       const int* __restrict__ degs, float* __restrict__ dinv) {
    const int CH = 30;
    int t = threadIdx.x;
    int base = t * CH;
    int s = 0;
#pragma unroll 5
    for (int i = 0; i < CH; i++) {
        int idx = base + i;
        if (idx < NN) s += cnt[idx];
    }
    int lane = t & 31, wid = t >> 5;
    int v = s;
#pragma unroll
    for (int o = 1; o < 32; o <<= 1) {
        int u = __shfl_up_sync(~0u, v, o);
        if (lane >= o) v += u;
    }
    __shared__ int wt[32];
    if (lane == 31) wt[wid] = v;
    __syncthreads();
    if (wid == 0) {
        int w = wt[lane];
#pragma unroll
        for (int o = 1; o < 32; o <<= 1) {
            int u = __shfl_up_sync(~0u, w, o);
            if (lane >= o) w += u;
        }
        wt[lane] = w;
    }
    __syncthreads();
    int pre = v - s + (wid ? wt[wid - 1] : 0);
    int run = pre;
#pragma unroll 5
    for (int i = 0; i < CH; i++) {
        int idx = base + i;
        if (idx < NN) {
            off[idx] = run;
            cur[idx] = run;
            int dg = degs[idx];
            dinv[idx] = (dg > 0) ? rsqrtf((float)dg) : 0.f;
            run += cnt[idx];
        }
    }
    if (t == 1023) off[NN] = run;
}

// scatter src VALUES per dst segment (order nondeterministic, multiset isn't)
__global__ void k_fill(const int* src, const int* dst, int* cur, int* esrc) {
    int e = blockIdx.x * blockDim.x + threadIdx.x;
    if (e >= NE) return;
    int p = atomicAdd(&cur[dst[e]], 1);
    esrc[p] = src[e];
}

// sort values within each segment -> deterministic order
__global__ void k_sortseg(const int* __restrict__ off, int* __restrict__ esrc) {
    int n = blockIdx.x * blockDim.x + threadIdx.x;
    if (n >= NN) return;
    int b = off[n], e = off[n + 1];
    for (int i = b + 1; i < e; i++) {
        int v = esrc[i];
        int j = i - 1;
        while (j >= b && esrc[j] > v) { esrc[j + 1] = esrc[j]; j--; }
        esrc[j + 1] = v;
    }
}

// ---------------- GEMM ----------------
struct GP {
    const float* A;
    const float* B;
    float* C;
    const float* tl;
    const float* lb;
    const float* gb;
    int lda, ldb, ldc, K, M;
};
struct GP4 { GP g[4]; };

// BM=128, BN=64, BK=16, 256 threads, 8x4/thread, double-buffered smem.
// NSLOT: how many z-slices. EPI==1: C := lrelu(acc + gb + lrelu(tl+lb) + id)
template <int EPI, int NSLOT>
__global__ void __launch_bounds__(256)
k_gemm(GP4 p, const float* __restrict__ id) {
    GP g = p.g[NSLOT == 1 ? 0 : blockIdx.z];
    int bcol = blockIdx.x * 64;
    if (bcol >= g.M) return;
    __shared__ float sA[2][16][128];
    __shared__ float sB[2][16][64];
    int tid = threadIdx.x;
    int tx = tid & 15, ty = tid >> 4;
    int brow = blockIdx.y * 128;
    const int K = g.K, M = g.M;

    const int ar0 = tid >> 2, akq = (tid & 3) * 4;
    const int ar1 = (tid + 256) >> 2;
    const int bkr = tid >> 4, bcq = (tid & 15) * 4;

    float4 pA0, pA1, pB;

#define LOAD_TILE(k0)                                                          \
    do {                                                                       \
        pA0 = make_float4(0.f, 0.f, 0.f, 0.f);                                 \
        pA1 = make_float4(0.f, 0.f, 0.f, 0.f);                                 \
        pB  = make_float4(0.f, 0.f, 0.f, 0.f);                                 \
        if (brow + ar0 < NN) {                                                 \
            const float* ap = g.A + (size_t)(brow + ar0) * g.lda + (k0) + akq; \
            if ((k0) + akq + 3 < K) pA0 = *(const float4*)ap;                  \
            else {                                                             \
                if ((k0) + akq + 0 < K) pA0.x = ap[0];                         \
                if ((k0) + akq + 1 < K) pA0.y = ap[1];                         \
                if ((k0) + akq + 2 < K) pA0.z = ap[2];                         \
                if ((k0) + akq + 3 < K) pA0.w = ap[3];                         \
            }                                                                  \
        }                                                                      \
        if (brow + ar1 < NN) {                                                 \
            const float* ap = g.A + (size_t)(brow + ar1) * g.lda + (k0) + akq; \
            if ((k0) + akq + 3 < K) pA1 = *(const float4*)ap;                  \
            else {                                                             \
                if ((k0) + akq + 0 < K) pA1.x = ap[0];                         \
                if ((k0) + akq + 1 < K) pA1.y = ap[1];                         \
                if ((k0) + akq + 2 < K) pA1.z = ap[2];                         \
                if ((k0) + akq + 3 < K) pA1.w = ap[3];                         \
            }                                                                  \
        }                                                                      \
        if ((k0) + bkr < K) {                                                  \
            const float* bp = g.B + (size_t)((k0) + bkr) * g.ldb + bcol + bcq; \
            if (bcol + bcq + 3 < M) pB = *(const float4*)bp;                   \
            else {                                                             \
                if (bcol + bcq + 0 < M) pB.x = bp[0];                          \
                if (bcol + bcq + 1 < M) pB.y = bp[1];                          \
                if (bcol + bcq + 2 < M) pB.z = bp[2];                          \
                if (bcol + bcq + 3 < M) pB.w = bp[3];                          \
            }                                                                  \
        }                                                                      \
    } while (0)

#define STORE_TILE(buf)                                                        \
    do {                                                                       \
        sA[buf][akq + 0][ar0] = pA0.x;                                         \
        sA[buf][akq + 1][ar0] = pA0.y;                                         \
        sA[buf][akq + 2][ar0] = pA0.z;                                         \
        sA[buf][akq + 3][ar0] = pA0.w;                                         \
        sA[buf][akq + 0][ar1] = pA1.x;                                         \
        sA[buf][akq + 1][ar1] = pA1.y;                                         \
        sA[buf][akq + 2][ar1] = pA1.z;                                         \
        sA[buf][akq + 3][ar1] = pA1.w;                                         \
        *(float4*)&sB[buf][bkr][bcq] = pB;                                     \
    } while (0)

    float acc[8][4] = {};
    LOAD_TILE(0);
    STORE_TILE(0);
    __syncthreads();
    int buf = 0;

    for (int k0 = 0; k0 < K; k0 += 16) {
        int nk = k0 + 16;
        if (nk < K) LOAD_TILE(nk);
#pragma unroll
        for (int kk = 0; kk < 16; kk++) {
            float4 a0 = *(const float4*)&sA[buf][kk][ty * 8];
            float4 a1 = *(const float4*)&sA[buf][kk][ty * 8 + 4];
            float4 b  = *(const float4*)&sB[buf][kk][tx * 4];
            float a[8] = {a0.x, a0.y, a0.z, a0.w, a1.x, a1.y, a1.z, a1.w};
            float bb[4] = {b.x, b.y, b.z, b.w};
#pragma unroll
            for (int i = 0; i < 8; i++)
#pragma unroll
                for (int j = 0; j < 4; j++)
                    acc[i][j] += a[i] * bb[j];
        }
        if (nk < K) {
            STORE_TILE(buf ^ 1);
            __syncthreads();
            buf ^= 1;
        }
    }
#undef LOAD_TILE
#undef STORE_TILE

#pragma unroll
    for (int i = 0; i < 8; i++) {
        int r = brow + ty * 8 + i;
        if (r >= NN) continue;
#pragma unroll
        for (int j = 0; j < 4; j++) {
            int c = bcol + tx * 4 + j;
            if (c >= M) continue;
            if (EPI == 0) {
                g.C[(size_t)r * g.ldc + c] = acc[i][j];
            } else {
                size_t lin = (size_t)r * 64 + c;
                float xh = g.tl[lin] + g.lb[c];
                xh = (xh > 0.f) ? xh : 0.01f * xh;
                xh += id[lin];
                float v = acc[i][j] + g.gb[c] + xh;
                g.C[lin] = (v > 0.f) ? v : 0.01f * v;
            }
        }
    }
}

// ---------------- combined tanh + l2norm ----------------
__global__ void __launch_bounds__(256)
k_tanh2(float* __restrict__ xv, const float* __restrict__ bv,
        float* __restrict__ xt, const float* __restrict__ bt) {
    int w = (blockIdx.x * blockDim.x + threadIdx.x) >> 5;
    int lane = threadIdx.x & 31;
    if (w >= 2 * NN) return;
    float* row;
    const float* b;
    int dim;
    if (w < NN) { row = xv + (size_t)w * LV; b = bv; dim = LV; }
    else        { row = xt + (size_t)(w - NN) * LT; b = bt; dim = LT; }
    float v[8];
    float ss = 0.f;
#pragma unroll
    for (int j = 0; j < 8; j++) {
        v[j] = 0.f;
        int c = lane + 32 * j;
        if (c < dim) {
            float t = tanhf(row[c] + b[c]);
            v[j] = t;
            ss += t * t;
        }
    }
#pragma unroll
    for (int o = 16; o; o >>= 1) ss += __shfl_xor_sync(~0u, ss, o);
    float sc = 1.f / fmaxf(sqrtf(ss), 1e-12f);
#pragma unroll
    for (int j = 0; j < 8; j++) {
        int c = lane + 32 * j;
        if (c < dim) row[c] = v[j] * sc;
    }
}

// ---------------- vector helpers ----------------
template <int VEC>
__device__ __forceinline__ void ldrow(const float* __restrict__ p, float* v) {
    if (VEC == 8) {
        float4 a = *(const float4*)p;
        float4 b = *(const float4*)(p + 4);
        v[0] = a.x; v[1] = a.y; v[2] = a.z; v[3] = a.w;
        v[4] = b.x; v[5] = b.y; v[6] = b.z; v[7] = b.w;
    } else if (VEC == 4) {
        float4 a = *(const float4*)p;
        v[0] = a.x; v[1] = a.y; v[2] = a.z; v[3] = a.w;
    } else {
        float2 a = *(const float2*)p;
        v[0] = a.x; v[1] = a.y;
    }
}

template <int VEC>
__device__ __forceinline__ void strow(float* __restrict__ p, const float* v) {
    if (VEC == 8) {
        *(float4*)p       = make_float4(v[0], v[1], v[2], v[3]);
        *(float4*)(p + 4) = make_float4(v[4], v[5], v[6], v[7]);
    } else if (VEC == 4) {
        *(float4*)p = make_float4(v[0], v[1], v[2], v[3]);
    } else {
        *(float2*)p = make_float2(v[0], v[1]);
    }
}

// ---------------- GAT (single-pass online softmax) ----------------
template <int VEC>
__device__ __forceinline__ void gat_update(const float* v, float di,
                                           const float (&hd)[VEC], float (&acc)[VEC],
                                           float& m, float& denom) {
    float d = 0.f;
#pragma unroll
    for (int j = 0; j < VEC; j++) {
        float lr = (v[j] > 0.f) ? v[j] : 0.01f * v[j];
        d += hd[j] * lr;
    }
#pragma unroll
    for (int o = 16; o; o >>= 1) d += __shfl_xor_sync(~0u, d, o);
    float t = d * di;
    float gate = 1.f / (1.f + __expf(-t));
    float lg = d * gate;
    if (lg > m) {
        float sc = __expf(m - lg);
        denom *= sc;
#pragma unroll
        for (int j = 0; j < VEC; j++) acc[j] *= sc;
        m = lg;
    }
    float w = __expf(lg - m);
    denom += w;
#pragma unroll
    for (int j = 0; j < VEC; j++) acc[j] += w * v[j];
}

template <int VEC>
__device__ __forceinline__ void gat_node(const float* __restrict__ hc, int dim,
                                         const int* __restrict__ esrc, int b0, int b1,
                                         const float* __restrict__ dinv,
                                         const float* __restrict__ bias,
                                         float* __restrict__ out, int n, int lane) {
    const int UN = (VEC == 2) ? 8 : 4;
    int c0 = lane * VEC;
    bool valid = c0 < dim;
    float hd[VEC];
#pragma unroll
    for (int j = 0; j < VEC; j++) hd[j] = 0.f;
    if (valid) ldrow<VEC>(hc + (size_t)n * dim + c0, hd);

    float m = -1e30f, denom = 0.f;
    float acc[VEC];
#pragma unroll
    for (int j = 0; j < VEC; j++) acc[j] = 0.f;

    int p = b0;
    for (; p + UN - 1 < b1; p += UN) {
        int s[UN];
        float di[UN];
        float v[UN][VEC];
#pragma unroll
        for (int q = 0; q < UN; q++) s[q] = esrc[p + q];
#pragma unroll
        for (int q = 0; q < UN; q++) di[q] = dinv[s[q]];
#pragma unroll
        for (int q = 0; q < UN; q++) {
#pragma unroll
            for (int j = 0; j < VEC; j++) v[q][j] = 0.f;
            if (valid) ldrow<VEC>(hc + (size_t)s[q] * dim + c0, v[q]);
        }
#pragma unroll
        for (int q = 0; q < UN; q++)
            gat_update<VEC>(v[q], di[q], hd, acc, m, denom);
    }
    for (; p < b1; p++) {
        int s = esrc[p];
        float di = dinv[s];
        float v[VEC];
#pragma unroll
        for (int j = 0; j < VEC; j++) v[j] = 0.f;
        if (valid) ldrow<VEC>(hc + (size_t)s * dim + c0, v);
        gat_update<VEC>(v, di, hd, acc, m, denom);
    }

    float inv = 1.f / (denom + 1e-16f);
    float val[VEC];
    float ss = 0.f;
#pragma unroll
    for (int j = 0; j < VEC; j++) {
        val[j] = 0.f;
        if (valid) {
            float v = acc[j] * inv + bias[c0 + j];
            val[j] = v;
            ss += v * v;
        }
    }
#pragma unroll
    for (int o = 16; o; o >>= 1) ss += __shfl_xor_sync(~0u, ss, o);
    float sc = 1.f / fmaxf(sqrtf(ss), 1e-12f);
    if (valid) {
        float res[VEC];
#pragma unroll
        for (int j = 0; j < VEC; j++) {
            float v = val[j] * sc;
            res[j] = (v > 0.f) ? v : 0.01f * v;
        }
        strow<VEC>(out + (size_t)n * dim + c0, res);
    }
}

__global__ void __launch_bounds__(128)
k_gat1(const float* __restrict__ hcv, const float* __restrict__ hct,
       const int* __restrict__ esrc, const int* __restrict__ off,
       const float* __restrict__ dinv,
       const float* __restrict__ bv, const float* __restrict__ bt,
       float* __restrict__ ov, float* __restrict__ ot) {
    int w = (blockIdx.x * blockDim.x + threadIdx.x) >> 5;
    int lane = threadIdx.x & 31;
    if (w >= 2 * NN) return;
    if (w < NN) {
        gat_node<8>(hcv, LV, esrc, off[w], off[w + 1], dinv, bv, ov, w, lane);
    } else {
        int n = w - NN;
        gat_node<4>(hct, LT, esrc, off[n], off[n + 1], dinv, bt, ot, n, lane);
    }
}

__global__ void __launch_bounds__(128)
k_gat2(const float* __restrict__ hcv, const float* __restrict__ hct,
       const int* __restrict__ esrc, const int* __restrict__ off,
       const float* __restrict__ dinv,
       const float* __restrict__ bv, const float* __restrict__ bt,
       float* __restrict__ ov, float* __restrict__ ot) {
    int w = (blockIdx.x * blockDim.x + threadIdx.x) >> 5;
    int lane = threadIdx.x & 31;
    if (w >= 2 * NN) return;
    if (w < NN) {
        gat_node<2>(hcv, DX, esrc, off[w], off[w + 1], dinv, bv, ov, w, lane);
    } else {
        int n = w - NN;
        gat_node<2>(hct, DX, esrc, off[n], off[n + 1], dinv, bt, ot, n, lane);
    }
}

// output: [representation | v_rep | t_rep]
__global__ void __launch_bounds__(256)
k_final(const float* __restrict__ vx1, const float* __restrict__ vx2,
        const float* __restrict__ tx1, const float* __restrict__ tx2,
        float* __restrict__ out, int out_size) {
    int i = blockIdx.x * blockDim.x + threadIdx.x;
    if (i >= NN * DX) return;
    int n = i >> 6, c = i & 63;
    float a1 = vx1[i], a2 = vx2[i], b1 = tx1[i], b2 = tx2[i];
    size_t base = (size_t)n * 128;
    out[base + c]      = (a1 + b1) * 0.5f;
    out[base + 64 + c] = (a2 + b2) * 0.5f;
    if (out_size >= 2 * NN * 128) {
        out[(size_t)NN * 128 + base + c]      = a1;
        out[(size_t)NN * 128 + base + 64 + c] = a2;
    }
    if (out_size >= 3 * NN * 128) {
        out[(size_t)2 * NN * 128 + base + c]      = b1;
        out[(size_t)2 * NN * 128 + base + 64 + c] = b2;
    }
}

// ---------------- host side ----------------
extern "C" void kernel_launch(void* const* d_in, const int* in_sizes, int n_in,
                              void* d_out, int out_size) {
    static float* F = nullptr;
    static int*   I = nullptr;
    if (!F) {
        cudaGetSymbolAddress((void**)&F, g_farena);
        cudaGetSymbolAddress((void**)&I, g_iarena);
    }

    float* x_v  = F;
    float* hc_v = F + 7680000;
    float* h_v  = F + 15360000;
    float* x_t  = F + 23040000;
    float* hc_t = F + 26040000;
    float* h_t  = F + 29040000;
    float* tl_v = F + 32040000;
    float* tl_t = F + 33960000;
    float* vx1  = F + 35880000;
    float* vx2  = F + 37800000;
    float* tx1  = F + 39720000;
    float* tx2  = F + 41640000;
    float* dinv = F + 43560000;

    int* src  = I;
    int* dst  = I + NE;
    int* esrc = I + 2 * NE;
    int* cnt  = I + 3 * NE;          // NN+1
    int* degs = cnt + (NN + 1);      // NN
    int* off  = degs + NN;           // NN+1
    int* cur  = off + (NN + 1);      // NN
    int* is64 = cur + NN;

    const float* feat  = (const float*)d_in[0];
    const void*  ei    = d_in[1];
    const float* idemb = (const float*)d_in[2];
    void* const* PV = d_in + 3;
    void* const* PT = d_in + 17;

#define PW(P, i) ((const float*)P[i])
#define GP0 {nullptr, nullptr, nullptr, nullptr, nullptr, nullptr, 0, 0, 0, 0, 0}

    dim3 blk(256);
    int gy = (NN + 127) / 128;
    int warp2_grid = (2 * NN * 32 + 255) / 256;
    int gat_grid = (2 * NN * 32 + 127) / 128;

    k_zero_i<<<(2 * NN + 256) / 256, 256>>>(cnt, 2 * NN + 1);
    k_detect<<<1, 1>>>(ei, is64);
    k_convert_hist<<<(NE + 255) / 256, 256>>>(ei, src, dst, cnt, degs, is64);

    // S1: mlp GEMM (z: 0=v, 1=t)
    {
        GP4 p = {{
            {feat, PW(PV, 0), x_v, nullptr, nullptr, nullptr, FDIM, LV, LV, 128, LV},
            {feat + 128, PW(PT, 0), x_t, nullptr, nullptr, nullptr, FDIM, LT, LT, 64, LT},
            GP0, GP0}};
        k_gemm<0, 2><<<dim3(4, gy, 2), blk>>>(p, nullptr);
    }
    // S2: tanh + l2norm
    k_tanh2<<<warp2_grid, 256>>>(x_v, PW(PV, 1), x_t, PW(PT, 1));
    // S3: c1 + l1 batched (z: 0=v-c1, 1=t-c1, 2=v-l1, 3=t-l1)
    {
        GP4 p = {{
            {x_v, PW(PV, 2), hc_v, nullptr, nullptr, nullptr, LV, LV, LV, LV, LV},
            {x_t, PW(PT, 2), hc_t, nullptr, nullptr, nullptr, LT, LT, LT, LT, LT},
            {x_v, PW(PV, 4), tl_v, nullptr, nullptr, nullptr, LV, DX, DX, LV, DX},
            {x_t, PW(PT, 4), tl_t, nullptr, nullptr, nullptr, LT, DX, DX, LT, DX}}};
        k_gemm<0, 4><<<dim3(4, gy, 4), blk>>>(p, nullptr);
    }

    // graph build tail
    k_scan<<<1, 1024>>>(cnt, off, cur, degs, dinv);
    k_fill<<<(NE + 255) / 256, 256>>>(src, dst, cur, esrc);
    k_sortseg<<<(NN + 255) / 256, 256>>>(off, esrc);

    // S4: GAT layer 1
    k_gat1<<<gat_grid, 128>>>(hc_v, hc_t, esrc, off, dinv, PW(PV, 3), PW(PT, 3), h_v, h_t);

    // S5: g1 GEMM + combine -> x1
    {
        GP4 p = {{
            {h_v, PW(PV, 6), vx1, tl_v, PW(PV, 5), PW(PV, 7), LV, DX, DX, LV, DX},
            {h_t, PW(PT, 6), tx1, tl_t, PW(PT, 5), PW(PT, 7), LT, DX, DX, LT, DX},
            GP0, GP0}};
        k_gemm<1, 2><<<dim3(1, gy, 2), blk>>>(p, idemb);
    }
    // S6: c2 + l2 batched
    {
        GP4 p = {{
            {vx1, PW(PV, 8), hc_v, nullptr, nullptr, nullptr, DX, DX, DX, DX, DX},
            {tx1, PW(PT, 8), hc_t, nullptr, nullptr, nullptr, DX, DX, DX, DX, DX},
            {vx1, PW(PV, 10), tl_v, nullptr, nullptr, nullptr, DX, DX, DX, DX, DX},
            {tx1, PW(PT, 10), tl_t, nullptr, nullptr, nullptr, DX, DX, DX, DX, DX}}};
        k_gemm<0, 4><<<dim3(1, gy, 4), blk>>>(p, nullptr);
    }
    // S7: GAT layer 2
    k_gat2<<<gat_grid, 128>>>(hc_v, hc_t, esrc, off, dinv, PW(PV, 9), PW(PT, 9), h_v, h_t);

    // S8: g2 GEMM + combine -> x2
    {
        GP4 p = {{
            {h_v, PW(PV, 12), vx2, tl_v, PW(PV, 11), PW(PV, 13), DX, DX, DX, DX, DX},
            {h_t, PW(PT, 12), tx2, tl_t, PW(PT, 11), PW(PT, 13), DX, DX, DX, DX, DX},
            GP0, GP0}};
        k_gemm<1, 2><<<dim3(1, gy, 2), blk>>>(p, idemb);
    }

    k_final<<<(NN * DX + 255) / 256, 256>>>(vx1, vx2, tx1, tx2, (float*)d_out, out_size);
#undef PW
#undef GP0
}